// round 15
// baseline (speedup 1.0000x reference)
#include <cuda_runtime.h>
#include <cuda_fp16.h>
#include <math.h>
#include <stdint.h>

// Problem constants (fixed by the reference)
#define BB 4
#define SS 2048
#define DD 1024
#define HH 16
#define DKK 64
#define MROWS (BB * SS)        // 8192
#define QKV_ELEMS (MROWS * DD) // 8.4M per tensor

// fp16 copies of inputs (converted once per launch)
static __device__ __half g_q16[QKV_ELEMS];
static __device__ __half g_k16[QKV_ELEMS];
static __device__ __half g_v16[QKV_ELEMS];
static __device__ __half g_w16[4 * DD * DD];       // wq(pre-scaled), wk, wv, wo
// fp16 intermediates: Q,K,V in [B,H,S,DK] layout, contiguous
static __device__ __half g_QKV[3 * QKV_ELEMS];
static __device__ __half g_X[BB * SS * DD];        // attention output [B,S,D]

// ===========================================================================
// helpers
// ===========================================================================
__device__ __forceinline__ uint32_t smem_u32(const void* p) {
    uint32_t a;
    asm("{ .reg .u64 t; cvta.to.shared.u64 t, %1; cvt.u32.u64 %0, t; }"
        : "=r"(a) : "l"(p));
    return a;
}

__device__ __forceinline__ uint32_t packh2(float lo, float hi) {
    __half2 h = __float22half2_rn(make_float2(lo, hi));
    return *reinterpret_cast<uint32_t*>(&h);
}

// packed half2 exp2 straight from two fp32 scores (no bias needed:
// softmax is invariant to the constant factor, p = 2^s fits fp16)
__device__ __forceinline__ uint32_t h2exp2(float a, float b) {
    uint32_t h = packh2(a, b);
    uint32_t r;
    asm("ex2.approx.f16x2 %0, %1;" : "=r"(r) : "r"(h));
    return r;
}

__device__ __forceinline__ float2 h22f2(uint32_t u) {
    __half2 h = *reinterpret_cast<__half2*>(&u);
    return __half22float2(h);
}

// swizzled smem addr, rows of 8 x 16B chunks (128B rows)
__device__ __forceinline__ uint32_t swz8(uint32_t base, int row, int ch) {
    return base + (((row << 3) | (ch ^ (row & 7))) << 4);
}

__device__ __forceinline__ void ldm_x4(uint32_t r[4], uint32_t addr) {
    asm volatile("ldmatrix.sync.aligned.m8n8.x4.shared.b16 {%0,%1,%2,%3}, [%4];"
        : "=r"(r[0]), "=r"(r[1]), "=r"(r[2]), "=r"(r[3]) : "r"(addr));
}
__device__ __forceinline__ void ldm_x4_t(uint32_t r[4], uint32_t addr) {
    asm volatile("ldmatrix.sync.aligned.m8n8.x4.trans.shared.b16 {%0,%1,%2,%3}, [%4];"
        : "=r"(r[0]), "=r"(r[1]), "=r"(r[2]), "=r"(r[3]) : "r"(addr));
}

__device__ __forceinline__ void mma_f16(float c[4], const uint32_t a[4],
                                        uint32_t b0, uint32_t b1) {
    asm volatile(
        "mma.sync.aligned.m16n8k16.row.col.f32.f16.f16.f32 "
        "{%0,%1,%2,%3}, {%4,%5,%6,%7}, {%8,%9}, {%0,%1,%2,%3};\n"
        : "+f"(c[0]), "+f"(c[1]), "+f"(c[2]), "+f"(c[3])
        : "r"(a[0]), "r"(a[1]), "r"(a[2]), "r"(a[3]), "r"(b0), "r"(b1));
}

#define STSV4(addr, r0, r1, r2, r3) \
    asm volatile("st.shared.v4.b32 [%0], {%1,%2,%3,%4};" \
        :: "r"(addr), "r"(r0), "r"(r1), "r"(r2), "r"(r3) : "memory")

#define CP_ASYNC16(dst, src) \
    asm volatile("cp.async.cg.shared.global [%0], [%1], 16;" \
        :: "r"(dst), "l"(src) : "memory")
#define CP_COMMIT() asm volatile("cp.async.commit_group;" ::: "memory")
#define CP_WAIT(n)  asm volatile("cp.async.wait_group %0;" :: "n"(n) : "memory")

// byte sizes (tiles are __half)
#define GEMM_TILE_BYTES   16384   // 128 rows x 64 halves x 2B
#define GEMM_BUF_BYTES    32768   // A tile + B tile
#define KV_TILE_BYTES      8192   // 64 rows x 64 halves x 2B
#define KV_BUF_BYTES      16384   // K tile + V tile (one kv tile)
#define STAGE_BYTES       32768   // 2 kv tiles per stage
#define Q_TILE_BYTES      16384
#define FLASH_SMEM (Q_TILE_BYTES + 3 * STAGE_BYTES)   // 114688 B (2 CTAs/SM)

// escale = 1/sqrt(dk) * log2(e), folded into w_q at conversion time
#define ESCALE 0.18033688f

// ===========================================================================
// fp32 -> fp16 conversion (optional scale), 4-way ILP, fused via z-dim
// ===========================================================================
__device__ __forceinline__ void cvt_body(const float4* __restrict__ s,
                                         uint2* __restrict__ d, int n4,
                                         float sc)
{
    const int stride = gridDim.x * blockDim.x;
    int i = blockIdx.x * blockDim.x + threadIdx.x;
    for (; i + 3 * stride < n4; i += 4 * stride) {
        float4 v0 = s[i];
        float4 v1 = s[i + stride];
        float4 v2 = s[i + 2 * stride];
        float4 v3 = s[i + 3 * stride];
        d[i]              = make_uint2(packh2(v0.x * sc, v0.y * sc), packh2(v0.z * sc, v0.w * sc));
        d[i + stride]     = make_uint2(packh2(v1.x * sc, v1.y * sc), packh2(v1.z * sc, v1.w * sc));
        d[i + 2 * stride] = make_uint2(packh2(v2.x * sc, v2.y * sc), packh2(v2.z * sc, v2.w * sc));
        d[i + 3 * stride] = make_uint2(packh2(v3.x * sc, v3.y * sc), packh2(v3.z * sc, v3.w * sc));
    }
    for (; i < n4; i += stride) {
        float4 v = s[i];
        d[i] = make_uint2(packh2(v.x * sc, v.y * sc), packh2(v.z * sc, v.w * sc));
    }
}

__global__ void cvt16_3(const float4* __restrict__ s0, const float4* __restrict__ s1,
                        const float4* __restrict__ s2,
                        uint2* __restrict__ d0, uint2* __restrict__ d1,
                        uint2* __restrict__ d2, int n4)
{
    const float4* s = (blockIdx.z == 0) ? s0 : (blockIdx.z == 1) ? s1 : s2;
    uint2*        d = (blockIdx.z == 0) ? d0 : (blockIdx.z == 1) ? d1 : d2;
    cvt_body(s, d, n4, 1.0f);
}

// z==0 is w_q: pre-scale by ESCALE in fp32 (better than post-hoc fp16 mul)
__global__ void cvt16_4(const float4* __restrict__ s0, const float4* __restrict__ s1,
                        const float4* __restrict__ s2, const float4* __restrict__ s3,
                        uint2* __restrict__ dbase, int n4)
{
    const float4* s = (blockIdx.z == 0) ? s0 : (blockIdx.z == 1) ? s1
                    : (blockIdx.z == 2) ? s2 : s3;
    const float sc = (blockIdx.z == 0) ? ESCALE : 1.0f;
    cvt_body(s, dbase + (size_t)blockIdx.z * n4, n4, sc);
}

// ===========================================================================
// GEMM body: Y = X @ W^T, all-fp16 inputs (K-contig). Block 128x128, 8 warps
// (2Mx4N), warp 64x32. K-chunk 64, cp.async 3-stage, ONE sync per chunk.
// MODE 0: Y float row-major.  MODE 1: Y half in [B,H,S,DK] layout.
// Dynamic smem: 3 buffers x 32KB = 96KB.
// ===========================================================================
template <int MODE>
__device__ __forceinline__ void gemm_body(const __half* __restrict__ X,
                                          const __half* __restrict__ W,
                                          void* __restrict__ Yv,
                                          char* smemRaw)
{
    const uint32_t sBase = smem_u32(smemRaw);

    const int tid  = threadIdx.x;
    const int wid  = tid >> 5;
    const int lane = tid & 31;
    const int g    = lane >> 2;
    const int t    = lane & 3;
    const int wm   = (wid >> 2) * 64;
    const int wn   = (wid & 3) * 32;
    const int bm0  = blockIdx.y * 128;
    const int bn0  = blockIdx.x * 128;

    float acc[4][4][4];
#pragma unroll
    for (int mt = 0; mt < 4; mt++)
#pragma unroll
        for (int nt = 0; nt < 4; nt++)
#pragma unroll
            for (int r = 0; r < 4; r++) acc[mt][nt][r] = 0.f;

    int grow[4], gch[4];
#pragma unroll
    for (int i = 0; i < 4; i++) {
        const int gi = i * 256 + tid;
        grow[i] = gi >> 3;
        gch[i]  = gi & 7;
    }

    auto load_chunk = [&](int c, int buf) {
        const uint32_t sA = sBase + buf * GEMM_BUF_BYTES;
        const uint32_t sB = sA + GEMM_TILE_BYTES;
        const int k0 = c * 64;
#pragma unroll
        for (int i = 0; i < 4; i++) {
            CP_ASYNC16(swz8(sA, grow[i], gch[i]),
                       &X[(size_t)(bm0 + grow[i]) * 1024 + k0 + gch[i] * 8]);
            CP_ASYNC16(swz8(sB, grow[i], gch[i]),
                       &W[(size_t)(bn0 + grow[i]) * 1024 + k0 + gch[i] * 8]);
        }
        CP_COMMIT();
    };

    load_chunk(0, 0);
    load_chunk(1, 1);

    int cur = 0;
    for (int c = 0; c < 16; c++) {
        if (c + 1 < 16) { CP_WAIT(1); }
        else            { CP_WAIT(0); }
        __syncthreads();
        if (c + 2 < 16) {
            int ld = cur - 1; if (ld < 0) ld += 3;
            load_chunk(c + 2, ld);
        }

        const uint32_t sA = sBase + cur * GEMM_BUF_BYTES;
        const uint32_t sB = sA + GEMM_TILE_BYTES;
#pragma unroll
        for (int ks = 0; ks < 4; ks++) {
            uint32_t af[4][4];
#pragma unroll
            for (int mt = 0; mt < 4; mt++) {
                const int row = wm + mt * 16 + (lane & 7) + (lane & 8);
                const int ch  = ks * 2 + (lane >> 4);
                ldm_x4(af[mt], swz8(sA, row, ch));
            }
#pragma unroll
            for (int np = 0; np < 2; np++) {
                const int row = wn + np * 16 + (lane & 7) + ((lane & 16) >> 1);
                const int ch  = ks * 2 + ((lane >> 3) & 1);
                uint32_t bf[4];
                ldm_x4(bf, swz8(sB, row, ch));
#pragma unroll
                for (int mt = 0; mt < 4; mt++) {
                    mma_f16(acc[mt][2 * np],     af[mt], bf[0], bf[1]);
                    mma_f16(acc[mt][2 * np + 1], af[mt], bf[2], bf[3]);
                }
            }
        }
        cur = (cur == 2) ? 0 : cur + 1;
    }

#pragma unroll
    for (int mt = 0; mt < 4; mt++) {
#pragma unroll
        for (int nt = 0; nt < 4; nt++) {
            const int r0 = bm0 + wm + mt * 16 + g;
            const int cN = bn0 + wn + nt * 8 + 2 * t;
#pragma unroll
            for (int hf = 0; hf < 2; hf++) {
                const int m = r0 + hf * 8;
                if (MODE == 0) {
                    float* Y = (float*)Yv;
                    *(float2*)&Y[(size_t)m * 1024 + cN] =
                        make_float2(acc[mt][nt][hf * 2], acc[mt][nt][hf * 2 + 1]);
                } else {
                    __half* Y = (__half*)Yv;
                    const int b  = m >> 11;
                    const int s  = m & (SS - 1);
                    const int h  = cN >> 6;
                    const int dk = cN & (DKK - 1);
                    *(uint32_t*)&Y[(((size_t)b * HH + h) * SS + s) * DKK + dk] =
                        packh2(acc[mt][nt][hf * 2], acc[mt][nt][hf * 2 + 1]);
                }
            }
        }
    }
}

// batched Q/K/V projections in one launch (z selects tensor)
__global__ void __launch_bounds__(256, 2)
gemm_qkv(const __half* __restrict__ x0, const __half* __restrict__ x1,
         const __half* __restrict__ x2, const __half* __restrict__ wb,
         __half* __restrict__ yb)
{
    extern __shared__ char smp[];
    const __half* X = (blockIdx.z == 0) ? x0 : (blockIdx.z == 1) ? x1 : x2;
    gemm_body<1>(X, wb + (size_t)blockIdx.z * DD * DD,
                 yb + (size_t)blockIdx.z * QKV_ELEMS, smp);
}

__global__ void __launch_bounds__(256, 2)
gemm_out(const __half* __restrict__ X, const __half* __restrict__ W,
         float* __restrict__ Y)
{
    extern __shared__ char smp[];
    gemm_body<0>(X, W, Y, smp);
}

// ===========================================================================
// Flash attention (causal), fp16 mma + ldmatrix. Fixed-scale softmax with NO
// bias: p = 2^s directly (max score ~9 -> p <= 512 << 65504; softmax is
// invariant to the constant factor). Q comes pre-scaled (ESCALE folded into
// w_q conversion). 2-tile cp.async stages (one barrier per 2 kv tiles),
// 3 stage buffers. Per-warp full-tile causal skip PLUS per-16-block triangle
// skip inside the diagonal tile (nblk valid blocks out of 4).
// 256 threads (8 warps); q-tile 128 rows (warp = 16 rows), kv-tile 64.
// Dynamic smem: Q 16KB + 3 x 32KB = 112KB (2 CTAs/SM).
// ===========================================================================
__global__ void __launch_bounds__(256, 2)
flash_h(const __half* __restrict__ Q, const __half* __restrict__ K,
        const __half* __restrict__ V, __half* __restrict__ O)
{
    extern __shared__ char fsm[];
    const uint32_t sQ  = smem_u32(fsm);
    const uint32_t sKV = sQ + Q_TILE_BYTES;

    const int tid  = threadIdx.x;
    const int wid  = tid >> 5;
    const int lane = tid & 31;
    const int g    = lane >> 2;
    const int t    = lane & 3;
    const int qb   = (gridDim.x - 1) - blockIdx.x;   // heavy CTAs first
    const int bh   = blockIdx.y;
    const int qrow0 = qb * 128;
    const int wrow  = wid * 16;
    const int qmaxw = qrow0 + wrow + 15;             // warp's last q row

    const __half* Qbase = Q + (size_t)bh * SS * DKK;
    const __half* Kbase = K + (size_t)bh * SS * DKK;
    const __half* Vbase = V + (size_t)bh * SS * DKK;

    const int kvrow = tid >> 1;                 // 0..127: K rows then V rows
    const int kvch0 = (tid & 1) * 4;

    const int smax = qb;                        // stages 0..qb (2 tiles each)

    // one commit per stage (empty past smax keeps group accounting uniform)
    auto load_stage = [&](int s) {
        if (s <= smax) {
            const uint32_t sbase = sKV + (s % 3) * STAGE_BYTES;
            const bool isV = kvrow >= 64;
            const int r = kvrow & 63;
#pragma unroll
            for (int tile = 0; tile < 2; tile++) {
                const int krow0 = (2 * s + tile) * 64;
                const __half* src = isV ? &Vbase[(size_t)(krow0 + r) * 64]
                                        : &Kbase[(size_t)(krow0 + r) * 64];
                const uint32_t dstb = sbase + tile * KV_BUF_BYTES
                                    + (isV ? KV_TILE_BYTES : 0);
#pragma unroll
                for (int i = 0; i < 4; i++) {
                    const int ch = kvch0 + i;
                    CP_ASYNC16(swz8(dstb, r, ch), src + ch * 8);
                }
            }
        }
        CP_COMMIT();
    };

    load_stage(0);
    load_stage(1);

    // fill Q tile (already pre-scaled at projection time)
#pragma unroll
    for (int i = 0; i < 4; i++) {
        const int gi = i * 256 + tid;
        const int r  = gi >> 3;
        const int ch = gi & 7;
        uint4 u = *(const uint4*)&Qbase[(size_t)(qrow0 + r) * 64 + ch * 8];
        STSV4(swz8(sQ, r, ch), u.x, u.y, u.z, u.w);
    }
    __syncthreads();

    uint32_t qf[4][4];
#pragma unroll
    for (int ks = 0; ks < 4; ks++) {
        const int row = wrow + (lane & 7) + (lane & 8);
        const int ch  = ks * 2 + (lane >> 4);
        ldm_x4(qf[ks], swz8(sQ, row, ch));
    }

    float oacc[8][4];
#pragma unroll
    for (int nt = 0; nt < 8; nt++)
#pragma unroll
        for (int r = 0; r < 4; r++) oacc[nt][r] = 0.f;
    float lrow0 = 0.f, lrow1 = 0.f;    // per-thread partial row sums

    // per-tile compute; nblk = number of valid 16-wide kv blocks
    auto compute_tile = [&](int krow0, uint32_t tbase) {
        if (krow0 > qmaxw) return;               // per-warp causal skip
        const uint32_t sK = tbase;
        const uint32_t sV = tbase + KV_TILE_BYTES;
        const int nblk = min(4, ((qmaxw - krow0) >> 4) + 1);

        // ---- S = Q K^T (pre-scaled, exp2 domain); skip dead blocks ----
        float sacc[8][4];
#pragma unroll
        for (int nt = 0; nt < 8; nt++)
#pragma unroll
            for (int r = 0; r < 4; r++) sacc[nt][r] = 0.f;

#pragma unroll
        for (int np = 0; np < 4; np++) {
            if (np >= nblk) break;
#pragma unroll
            for (int ks = 0; ks < 4; ks++) {
                const int row = np * 16 + (lane & 7) + ((lane & 16) >> 1);
                const int ch  = ks * 2 + ((lane >> 3) & 1);
                uint32_t kb[4];
                ldm_x4(kb, swz8(sK, row, ch));
                mma_f16(sacc[2 * np],     qf[ks], kb[0], kb[1]);
                mma_f16(sacc[2 * np + 1], qf[ks], kb[2], kb[3]);
            }
        }

        // causal mask (within valid blocks)
        const int r0g = qrow0 + wrow + g;
        const int r1g = r0g + 8;
        if (krow0 + 63 > qrow0 + wrow) {
#pragma unroll
            for (int nt = 0; nt < 8; nt++) {
                const int c0 = krow0 + nt * 8 + 2 * t;
                if (c0 > r0g)     sacc[nt][0] = -1e30f;
                if (c0 + 1 > r0g) sacc[nt][1] = -1e30f;
                if (c0 > r1g)     sacc[nt][2] = -1e30f;
                if (c0 + 1 > r1g) sacc[nt][3] = -1e30f;
            }
        }

        // ---- p = 2^s straight to fp16 (masked -> ex2(-inf) = 0) ----
        uint32_t pf[4][4];
#pragma unroll
        for (int kc = 0; kc < 4; kc++) {
            if (kc >= nblk) break;
            pf[kc][0] = h2exp2(sacc[2 * kc][0],     sacc[2 * kc][1]);
            pf[kc][1] = h2exp2(sacc[2 * kc][2],     sacc[2 * kc][3]);
            pf[kc][2] = h2exp2(sacc[2 * kc + 1][0], sacc[2 * kc + 1][1]);
            pf[kc][3] = h2exp2(sacc[2 * kc + 1][2], sacc[2 * kc + 1][3]);
            float2 f0 = h22f2(pf[kc][0]);
            float2 f2 = h22f2(pf[kc][2]);
            lrow0 += f0.x + f0.y + f2.x + f2.y;
            float2 f1 = h22f2(pf[kc][1]);
            float2 f3 = h22f2(pf[kc][3]);
            lrow1 += f1.x + f1.y + f3.x + f3.y;
        }

        // ---- O += P V (skip dead kv blocks) ----
#pragma unroll
        for (int kc = 0; kc < 4; kc++) {
            if (kc >= nblk) break;
#pragma unroll
            for (int dp = 0; dp < 4; dp++) {
                const int row = kc * 16 + (lane & 7) + (lane & 8);
                const int ch  = dp * 2 + (lane >> 4);
                uint32_t vb[4];
                ldm_x4_t(vb, swz8(sV, row, ch));
                mma_f16(oacc[2 * dp],     pf[kc], vb[0], vb[1]);
                mma_f16(oacc[2 * dp + 1], pf[kc], vb[2], vb[3]);
            }
        }
    };

    for (int s = 0; s <= smax; s++) {
        CP_WAIT(1);                 // stage s landed (s+1 in flight)
        __syncthreads();            // + proves stage s-1's buffer is free
        load_stage(s + 2);

        const uint32_t sbase = sKV + (s % 3) * STAGE_BYTES;
        compute_tile(2 * s * 64,       sbase);
        compute_tile((2 * s + 1) * 64, sbase + KV_BUF_BYTES);
    }

    // single quad-reduction of l at the end
    lrow0 += __shfl_xor_sync(0xffffffffu, lrow0, 1);
    lrow0 += __shfl_xor_sync(0xffffffffu, lrow0, 2);
    lrow1 += __shfl_xor_sync(0xffffffffu, lrow1, 1);
    lrow1 += __shfl_xor_sync(0xffffffffu, lrow1, 2);

    // epilogue -> O half [B,S,D]
    const int b = bh / HH;
    const int h = bh % HH;
    const float il0 = 1.0f / lrow0;
    const float il1 = 1.0f / lrow1;
    const int r0 = qrow0 + wrow + g;
#pragma unroll
    for (int nt = 0; nt < 8; nt++) {
        const int cN = h * DKK + nt * 8 + 2 * t;
        *(uint32_t*)&O[((size_t)b * SS + r0) * DD + cN] =
            packh2(oacc[nt][0] * il0, oacc[nt][1] * il0);
        *(uint32_t*)&O[((size_t)b * SS + r0 + 8) * DD + cN] =
            packh2(oacc[nt][2] * il1, oacc[nt][3] * il1);
    }
}

// ---------------------------------------------------------------------------
// Launch
// inputs: 0:q 1:k 2:v 3:mask 4:w_q 5:w_k 6:w_v 7:w_o ; out: [B,S,D] f32
// ---------------------------------------------------------------------------
extern "C" void kernel_launch(void* const* d_in, const int* in_sizes, int n_in,
                              void* d_out, int out_size)
{
    const float* q   = (const float*)d_in[0];
    const float* k   = (const float*)d_in[1];
    const float* v   = (const float*)d_in[2];
    // d_in[3] = mask (causal tril; handled analytically in-kernel)
    const float* w_q = (const float*)d_in[4];
    const float* w_k = (const float*)d_in[5];
    const float* w_v = (const float*)d_in[6];
    const float* w_o = (const float*)d_in[7];
    float* out = (float*)d_out;

    __half *q16, *k16, *v16, *w16, *qkv, *gX;
    cudaGetSymbolAddress((void**)&q16, g_q16);
    cudaGetSymbolAddress((void**)&k16, g_k16);
    cudaGetSymbolAddress((void**)&v16, g_v16);
    cudaGetSymbolAddress((void**)&w16, g_w16);
    cudaGetSymbolAddress((void**)&qkv, g_QKV);
    cudaGetSymbolAddress((void**)&gX, g_X);

    // fp32 -> fp16 conversions (2 fused launches, 4-way ILP; w_q pre-scaled)
    const int nx4 = QKV_ELEMS / 4;       // 2M float4 per q/k/v
    const int nw4 = DD * DD / 4;         // 256K float4 per weight
    cvt16_3<<<dim3(512, 1, 3), 256>>>((const float4*)q, (const float4*)k,
                                      (const float4*)v, (uint2*)q16,
                                      (uint2*)k16, (uint2*)v16, nx4);
    cvt16_4<<<dim3(256, 1, 4), 256>>>((const float4*)w_q, (const float4*)w_k,
                                      (const float4*)w_v, (const float4*)w_o,
                                      (uint2*)w16, nw4);

    const int gsmem = 3 * GEMM_BUF_BYTES;      // 98304 B
    cudaFuncSetAttribute(gemm_qkv, cudaFuncAttributeMaxDynamicSharedMemorySize, gsmem);
    cudaFuncSetAttribute(gemm_out, cudaFuncAttributeMaxDynamicSharedMemorySize, gsmem);
    cudaFuncSetAttribute(flash_h, cudaFuncAttributeMaxDynamicSharedMemorySize, FLASH_SMEM);

    // all three projections in ONE launch (single tail wave)
    gemm_qkv<<<dim3(DD / 128, MROWS / 128, 3), 256, gsmem>>>(q16, k16, v16, w16, qkv);

    flash_h<<<dim3(SS / 128, BB * HH), 256, FLASH_SMEM>>>(qkv, qkv + QKV_ELEMS,
                                                          qkv + 2 * QKV_ELEMS, gX);

    gemm_out<<<dim3(DD / 128, MROWS / 128), 256, gsmem>>>(gX, w16 + 3 * DD * DD, out);
}

// round 16
// speedup vs baseline: 1.0356x; 1.0356x over previous
#include <cuda_runtime.h>
#include <cuda_fp16.h>
#include <math.h>
#include <stdint.h>

// Problem constants (fixed by the reference)
#define BB 4
#define SS 2048
#define DD 1024
#define HH 16
#define DKK 64
#define MROWS (BB * SS)        // 8192
#define QKV_ELEMS (MROWS * DD) // 8.4M per tensor

// fp16 copies of inputs (converted once per launch)
static __device__ __half g_q16[QKV_ELEMS];
static __device__ __half g_k16[QKV_ELEMS];
static __device__ __half g_v16[QKV_ELEMS];
static __device__ __half g_w16[4 * DD * DD];       // wq(pre-scaled), wk, wv, wo
// fp16 intermediates: Q,K,V in [B,H,S,DK] layout, contiguous
static __device__ __half g_QKV[3 * QKV_ELEMS];
static __device__ __half g_X[BB * SS * DD];        // attention output [B,S,D]

// ===========================================================================
// helpers
// ===========================================================================
__device__ __forceinline__ uint32_t smem_u32(const void* p) {
    uint32_t a;
    asm("{ .reg .u64 t; cvta.to.shared.u64 t, %1; cvt.u32.u64 %0, t; }"
        : "=r"(a) : "l"(p));
    return a;
}

__device__ __forceinline__ uint32_t packh2(float lo, float hi) {
    __half2 h = __float22half2_rn(make_float2(lo, hi));
    return *reinterpret_cast<uint32_t*>(&h);
}

// packed half2 exp2 straight from two fp32 scores (no bias needed:
// softmax is invariant to the constant factor, p = 2^s fits fp16)
__device__ __forceinline__ uint32_t h2exp2(float a, float b) {
    uint32_t h = packh2(a, b);
    uint32_t r;
    asm("ex2.approx.f16x2 %0, %1;" : "=r"(r) : "r"(h));
    return r;
}

__device__ __forceinline__ float2 h22f2(uint32_t u) {
    __half2 h = *reinterpret_cast<__half2*>(&u);
    return __half22float2(h);
}

// swizzled smem addr, rows of 8 x 16B chunks (128B rows)
__device__ __forceinline__ uint32_t swz8(uint32_t base, int row, int ch) {
    return base + (((row << 3) | (ch ^ (row & 7))) << 4);
}

__device__ __forceinline__ void ldm_x4(uint32_t r[4], uint32_t addr) {
    asm volatile("ldmatrix.sync.aligned.m8n8.x4.shared.b16 {%0,%1,%2,%3}, [%4];"
        : "=r"(r[0]), "=r"(r[1]), "=r"(r[2]), "=r"(r[3]) : "r"(addr));
}
__device__ __forceinline__ void ldm_x4_t(uint32_t r[4], uint32_t addr) {
    asm volatile("ldmatrix.sync.aligned.m8n8.x4.trans.shared.b16 {%0,%1,%2,%3}, [%4];"
        : "=r"(r[0]), "=r"(r[1]), "=r"(r[2]), "=r"(r[3]) : "r"(addr));
}

__device__ __forceinline__ void mma_f16(float c[4], const uint32_t a[4],
                                        uint32_t b0, uint32_t b1) {
    asm volatile(
        "mma.sync.aligned.m16n8k16.row.col.f32.f16.f16.f32 "
        "{%0,%1,%2,%3}, {%4,%5,%6,%7}, {%8,%9}, {%0,%1,%2,%3};\n"
        : "+f"(c[0]), "+f"(c[1]), "+f"(c[2]), "+f"(c[3])
        : "r"(a[0]), "r"(a[1]), "r"(a[2]), "r"(a[3]), "r"(b0), "r"(b1));
}

#define STSV4(addr, r0, r1, r2, r3) \
    asm volatile("st.shared.v4.b32 [%0], {%1,%2,%3,%4};" \
        :: "r"(addr), "r"(r0), "r"(r1), "r"(r2), "r"(r3) : "memory")

#define CP_ASYNC16(dst, src) \
    asm volatile("cp.async.cg.shared.global [%0], [%1], 16;" \
        :: "r"(dst), "l"(src) : "memory")
#define CP_COMMIT() asm volatile("cp.async.commit_group;" ::: "memory")
#define CP_WAIT(n)  asm volatile("cp.async.wait_group %0;" :: "n"(n) : "memory")

// byte sizes (tiles are __half)
#define GEMM_TILE_BYTES   16384   // 128 rows x 64 halves x 2B
#define GEMM_BUF_BYTES    32768   // A tile + B tile
#define KV_TILE_BYTES      8192   // 64 rows x 64 halves x 2B
#define KV_BUF_BYTES      16384   // K tile + V tile (one kv tile)
#define STAGE_BYTES       32768   // 2 kv tiles per stage
#define Q_TILE_BYTES      16384
#define FLASH_SMEM (Q_TILE_BYTES + 3 * STAGE_BYTES)   // 114688 B (2 CTAs/SM)

// escale = 1/sqrt(dk) * log2(e), folded into w_q at conversion time
#define ESCALE 0.18033688f

// ===========================================================================
// fp32 -> fp16 conversion (optional scale), 4-way ILP, fused via z-dim
// ===========================================================================
__device__ __forceinline__ void cvt_body(const float4* __restrict__ s,
                                         uint2* __restrict__ d, int n4,
                                         float sc)
{
    const int stride = gridDim.x * blockDim.x;
    int i = blockIdx.x * blockDim.x + threadIdx.x;
    for (; i + 3 * stride < n4; i += 4 * stride) {
        float4 v0 = s[i];
        float4 v1 = s[i + stride];
        float4 v2 = s[i + 2 * stride];
        float4 v3 = s[i + 3 * stride];
        d[i]              = make_uint2(packh2(v0.x * sc, v0.y * sc), packh2(v0.z * sc, v0.w * sc));
        d[i + stride]     = make_uint2(packh2(v1.x * sc, v1.y * sc), packh2(v1.z * sc, v1.w * sc));
        d[i + 2 * stride] = make_uint2(packh2(v2.x * sc, v2.y * sc), packh2(v2.z * sc, v2.w * sc));
        d[i + 3 * stride] = make_uint2(packh2(v3.x * sc, v3.y * sc), packh2(v3.z * sc, v3.w * sc));
    }
    for (; i < n4; i += stride) {
        float4 v = s[i];
        d[i] = make_uint2(packh2(v.x * sc, v.y * sc), packh2(v.z * sc, v.w * sc));
    }
}

__global__ void cvt16_3(const float4* __restrict__ s0, const float4* __restrict__ s1,
                        const float4* __restrict__ s2,
                        uint2* __restrict__ d0, uint2* __restrict__ d1,
                        uint2* __restrict__ d2, int n4)
{
    const float4* s = (blockIdx.z == 0) ? s0 : (blockIdx.z == 1) ? s1 : s2;
    uint2*        d = (blockIdx.z == 0) ? d0 : (blockIdx.z == 1) ? d1 : d2;
    cvt_body(s, d, n4, 1.0f);
}

// z==0 is w_q: pre-scale by ESCALE in fp32 (better than post-hoc fp16 mul)
__global__ void cvt16_4(const float4* __restrict__ s0, const float4* __restrict__ s1,
                        const float4* __restrict__ s2, const float4* __restrict__ s3,
                        uint2* __restrict__ dbase, int n4)
{
    const float4* s = (blockIdx.z == 0) ? s0 : (blockIdx.z == 1) ? s1
                    : (blockIdx.z == 2) ? s2 : s3;
    const float sc = (blockIdx.z == 0) ? ESCALE : 1.0f;
    cvt_body(s, dbase + (size_t)blockIdx.z * n4, n4, sc);
}

// ===========================================================================
// GEMM body: Y = X @ W^T, all-fp16 inputs (K-contig). Block 128x128, 8 warps
// (2Mx4N), warp 64x32. K-chunk 64, cp.async 3-stage, ONE sync per chunk.
// MODE 0: Y float row-major.  MODE 1: Y half in [B,H,S,DK] layout.
// Dynamic smem: 3 buffers x 32KB = 96KB.
// ===========================================================================
template <int MODE>
__device__ __forceinline__ void gemm_body(const __half* __restrict__ X,
                                          const __half* __restrict__ W,
                                          void* __restrict__ Yv,
                                          char* smemRaw)
{
    const uint32_t sBase = smem_u32(smemRaw);

    const int tid  = threadIdx.x;
    const int wid  = tid >> 5;
    const int lane = tid & 31;
    const int g    = lane >> 2;
    const int t    = lane & 3;
    const int wm   = (wid >> 2) * 64;
    const int wn   = (wid & 3) * 32;
    const int bm0  = blockIdx.y * 128;
    const int bn0  = blockIdx.x * 128;

    float acc[4][4][4];
#pragma unroll
    for (int mt = 0; mt < 4; mt++)
#pragma unroll
        for (int nt = 0; nt < 4; nt++)
#pragma unroll
            for (int r = 0; r < 4; r++) acc[mt][nt][r] = 0.f;

    int grow[4], gch[4];
#pragma unroll
    for (int i = 0; i < 4; i++) {
        const int gi = i * 256 + tid;
        grow[i] = gi >> 3;
        gch[i]  = gi & 7;
    }

    auto load_chunk = [&](int c, int buf) {
        const uint32_t sA = sBase + buf * GEMM_BUF_BYTES;
        const uint32_t sB = sA + GEMM_TILE_BYTES;
        const int k0 = c * 64;
#pragma unroll
        for (int i = 0; i < 4; i++) {
            CP_ASYNC16(swz8(sA, grow[i], gch[i]),
                       &X[(size_t)(bm0 + grow[i]) * 1024 + k0 + gch[i] * 8]);
            CP_ASYNC16(swz8(sB, grow[i], gch[i]),
                       &W[(size_t)(bn0 + grow[i]) * 1024 + k0 + gch[i] * 8]);
        }
        CP_COMMIT();
    };

    load_chunk(0, 0);
    load_chunk(1, 1);

    int cur = 0;
    for (int c = 0; c < 16; c++) {
        if (c + 1 < 16) { CP_WAIT(1); }
        else            { CP_WAIT(0); }
        __syncthreads();
        if (c + 2 < 16) {
            int ld = cur - 1; if (ld < 0) ld += 3;
            load_chunk(c + 2, ld);
        }

        const uint32_t sA = sBase + cur * GEMM_BUF_BYTES;
        const uint32_t sB = sA + GEMM_TILE_BYTES;
#pragma unroll
        for (int ks = 0; ks < 4; ks++) {
            uint32_t af[4][4];
#pragma unroll
            for (int mt = 0; mt < 4; mt++) {
                const int row = wm + mt * 16 + (lane & 7) + (lane & 8);
                const int ch  = ks * 2 + (lane >> 4);
                ldm_x4(af[mt], swz8(sA, row, ch));
            }
#pragma unroll
            for (int np = 0; np < 2; np++) {
                const int row = wn + np * 16 + (lane & 7) + ((lane & 16) >> 1);
                const int ch  = ks * 2 + ((lane >> 3) & 1);
                uint32_t bf[4];
                ldm_x4(bf, swz8(sB, row, ch));
#pragma unroll
                for (int mt = 0; mt < 4; mt++) {
                    mma_f16(acc[mt][2 * np],     af[mt], bf[0], bf[1]);
                    mma_f16(acc[mt][2 * np + 1], af[mt], bf[2], bf[3]);
                }
            }
        }
        cur = (cur == 2) ? 0 : cur + 1;
    }

#pragma unroll
    for (int mt = 0; mt < 4; mt++) {
#pragma unroll
        for (int nt = 0; nt < 4; nt++) {
            const int r0 = bm0 + wm + mt * 16 + g;
            const int cN = bn0 + wn + nt * 8 + 2 * t;
#pragma unroll
            for (int hf = 0; hf < 2; hf++) {
                const int m = r0 + hf * 8;
                if (MODE == 0) {
                    float* Y = (float*)Yv;
                    *(float2*)&Y[(size_t)m * 1024 + cN] =
                        make_float2(acc[mt][nt][hf * 2], acc[mt][nt][hf * 2 + 1]);
                } else {
                    __half* Y = (__half*)Yv;
                    const int b  = m >> 11;
                    const int s  = m & (SS - 1);
                    const int h  = cN >> 6;
                    const int dk = cN & (DKK - 1);
                    *(uint32_t*)&Y[(((size_t)b * HH + h) * SS + s) * DKK + dk] =
                        packh2(acc[mt][nt][hf * 2], acc[mt][nt][hf * 2 + 1]);
                }
            }
        }
    }
}

// batched Q/K/V projections in one launch (z selects tensor)
__global__ void __launch_bounds__(256, 2)
gemm_qkv(const __half* __restrict__ x0, const __half* __restrict__ x1,
         const __half* __restrict__ x2, const __half* __restrict__ wb,
         __half* __restrict__ yb)
{
    extern __shared__ char smp[];
    const __half* X = (blockIdx.z == 0) ? x0 : (blockIdx.z == 1) ? x1 : x2;
    gemm_body<1>(X, wb + (size_t)blockIdx.z * DD * DD,
                 yb + (size_t)blockIdx.z * QKV_ELEMS, smp);
}

__global__ void __launch_bounds__(256, 2)
gemm_out(const __half* __restrict__ X, const __half* __restrict__ W,
         float* __restrict__ Y)
{
    extern __shared__ char smp[];
    gemm_body<0>(X, W, Y, smp);
}

// ===========================================================================
// Flash attention (causal), fp16 mma + ldmatrix. Fixed-scale softmax with NO
// bias: p = 2^s directly (max score ~9 -> p <= 512 << 65504; softmax is
// invariant to the constant factor). Q comes pre-scaled (ESCALE folded into
// w_q conversion). 2-tile cp.async stages (one barrier per 2 kv tiles),
// 3 stage buffers. Per-warp whole-tile causal skip; fully-unrolled loops
// (NO dynamic nblk bounds — R15 showed they defeat unrolling).
// 256 threads (8 warps); q-tile 128 rows (warp = 16 rows), kv-tile 64.
// Dynamic smem: Q 16KB + 3 x 32KB = 112KB (2 CTAs/SM).
// ===========================================================================
__global__ void __launch_bounds__(256, 2)
flash_h(const __half* __restrict__ Q, const __half* __restrict__ K,
        const __half* __restrict__ V, __half* __restrict__ O)
{
    extern __shared__ char fsm[];
    const uint32_t sQ  = smem_u32(fsm);
    const uint32_t sKV = sQ + Q_TILE_BYTES;

    const int tid  = threadIdx.x;
    const int wid  = tid >> 5;
    const int lane = tid & 31;
    const int g    = lane >> 2;
    const int t    = lane & 3;
    const int qb   = (gridDim.x - 1) - blockIdx.x;   // heavy CTAs first
    const int bh   = blockIdx.y;
    const int qrow0 = qb * 128;
    const int wrow  = wid * 16;
    const int qmaxw = qrow0 + wrow + 15;             // warp's last q row

    const __half* Qbase = Q + (size_t)bh * SS * DKK;
    const __half* Kbase = K + (size_t)bh * SS * DKK;
    const __half* Vbase = V + (size_t)bh * SS * DKK;

    const int kvrow = tid >> 1;                 // 0..127: K rows then V rows
    const int kvch0 = (tid & 1) * 4;

    const int smax = qb;                        // stages 0..qb (2 tiles each)

    // one commit per stage (empty past smax keeps group accounting uniform)
    auto load_stage = [&](int s) {
        if (s <= smax) {
            const uint32_t sbase = sKV + (s % 3) * STAGE_BYTES;
            const bool isV = kvrow >= 64;
            const int r = kvrow & 63;
#pragma unroll
            for (int tile = 0; tile < 2; tile++) {
                const int krow0 = (2 * s + tile) * 64;
                const __half* src = isV ? &Vbase[(size_t)(krow0 + r) * 64]
                                        : &Kbase[(size_t)(krow0 + r) * 64];
                const uint32_t dstb = sbase + tile * KV_BUF_BYTES
                                    + (isV ? KV_TILE_BYTES : 0);
#pragma unroll
                for (int i = 0; i < 4; i++) {
                    const int ch = kvch0 + i;
                    CP_ASYNC16(swz8(dstb, r, ch), src + ch * 8);
                }
            }
        }
        CP_COMMIT();
    };

    load_stage(0);
    load_stage(1);

    // fill Q tile (already pre-scaled at projection time)
#pragma unroll
    for (int i = 0; i < 4; i++) {
        const int gi = i * 256 + tid;
        const int r  = gi >> 3;
        const int ch = gi & 7;
        uint4 u = *(const uint4*)&Qbase[(size_t)(qrow0 + r) * 64 + ch * 8];
        STSV4(swz8(sQ, r, ch), u.x, u.y, u.z, u.w);
    }
    __syncthreads();

    uint32_t qf[4][4];
#pragma unroll
    for (int ks = 0; ks < 4; ks++) {
        const int row = wrow + (lane & 7) + (lane & 8);
        const int ch  = ks * 2 + (lane >> 4);
        ldm_x4(qf[ks], swz8(sQ, row, ch));
    }

    float oacc[8][4];
#pragma unroll
    for (int nt = 0; nt < 8; nt++)
#pragma unroll
        for (int r = 0; r < 4; r++) oacc[nt][r] = 0.f;
    float lrow0 = 0.f, lrow1 = 0.f;    // per-thread partial row sums

    // per-tile compute (fully unrolled; per-warp whole-tile skip only)
    auto compute_tile = [&](int krow0, uint32_t tbase) {
        if (krow0 > qmaxw) return;               // per-warp causal skip
        const uint32_t sK = tbase;
        const uint32_t sV = tbase + KV_TILE_BYTES;

        // ---- S = Q K^T (pre-scaled, exp2 domain) ----
        float sacc[8][4];
#pragma unroll
        for (int nt = 0; nt < 8; nt++)
#pragma unroll
            for (int r = 0; r < 4; r++) sacc[nt][r] = 0.f;

#pragma unroll
        for (int ks = 0; ks < 4; ks++) {
#pragma unroll
            for (int np = 0; np < 4; np++) {
                const int row = np * 16 + (lane & 7) + ((lane & 16) >> 1);
                const int ch  = ks * 2 + ((lane >> 3) & 1);
                uint32_t kb[4];
                ldm_x4(kb, swz8(sK, row, ch));
                mma_f16(sacc[2 * np],     qf[ks], kb[0], kb[1]);
                mma_f16(sacc[2 * np + 1], qf[ks], kb[2], kb[3]);
            }
        }

        // causal mask
        const int r0g = qrow0 + wrow + g;
        const int r1g = r0g + 8;
        if (krow0 + 63 > qrow0 + wrow) {
#pragma unroll
            for (int nt = 0; nt < 8; nt++) {
                const int c0 = krow0 + nt * 8 + 2 * t;
                if (c0 > r0g)     sacc[nt][0] = -1e30f;
                if (c0 + 1 > r0g) sacc[nt][1] = -1e30f;
                if (c0 > r1g)     sacc[nt][2] = -1e30f;
                if (c0 + 1 > r1g) sacc[nt][3] = -1e30f;
            }
        }

        // ---- p = 2^s straight to fp16 (masked -> ex2(-inf) = 0) ----
        uint32_t pf[4][4];
#pragma unroll
        for (int kc = 0; kc < 4; kc++) {
            pf[kc][0] = h2exp2(sacc[2 * kc][0],     sacc[2 * kc][1]);
            pf[kc][1] = h2exp2(sacc[2 * kc][2],     sacc[2 * kc][3]);
            pf[kc][2] = h2exp2(sacc[2 * kc + 1][0], sacc[2 * kc + 1][1]);
            pf[kc][3] = h2exp2(sacc[2 * kc + 1][2], sacc[2 * kc + 1][3]);
            float2 f0 = h22f2(pf[kc][0]);
            float2 f2 = h22f2(pf[kc][2]);
            lrow0 += f0.x + f0.y + f2.x + f2.y;
            float2 f1 = h22f2(pf[kc][1]);
            float2 f3 = h22f2(pf[kc][3]);
            lrow1 += f1.x + f1.y + f3.x + f3.y;
        }

        // ---- O += P V ----
#pragma unroll
        for (int kc = 0; kc < 4; kc++) {
#pragma unroll
            for (int dp = 0; dp < 4; dp++) {
                const int row = kc * 16 + (lane & 7) + (lane & 8);
                const int ch  = dp * 2 + (lane >> 4);
                uint32_t vb[4];
                ldm_x4_t(vb, swz8(sV, row, ch));
                mma_f16(oacc[2 * dp],     pf[kc], vb[0], vb[1]);
                mma_f16(oacc[2 * dp + 1], pf[kc], vb[2], vb[3]);
            }
        }
    };

    for (int s = 0; s <= smax; s++) {
        CP_WAIT(1);                 // stage s landed (s+1 in flight)
        __syncthreads();            // + proves stage s-1's buffer is free
        load_stage(s + 2);

        const uint32_t sbase = sKV + (s % 3) * STAGE_BYTES;
        compute_tile(2 * s * 64,       sbase);
        compute_tile((2 * s + 1) * 64, sbase + KV_BUF_BYTES);
    }

    // single quad-reduction of l at the end
    lrow0 += __shfl_xor_sync(0xffffffffu, lrow0, 1);
    lrow0 += __shfl_xor_sync(0xffffffffu, lrow0, 2);
    lrow1 += __shfl_xor_sync(0xffffffffu, lrow1, 1);
    lrow1 += __shfl_xor_sync(0xffffffffu, lrow1, 2);

    // epilogue -> O half [B,S,D]
    const int b = bh / HH;
    const int h = bh % HH;
    const float il0 = 1.0f / lrow0;
    const float il1 = 1.0f / lrow1;
    const int r0 = qrow0 + wrow + g;
#pragma unroll
    for (int nt = 0; nt < 8; nt++) {
        const int cN = h * DKK + nt * 8 + 2 * t;
        *(uint32_t*)&O[((size_t)b * SS + r0) * DD + cN] =
            packh2(oacc[nt][0] * il0, oacc[nt][1] * il0);
        *(uint32_t*)&O[((size_t)b * SS + r0 + 8) * DD + cN] =
            packh2(oacc[nt][2] * il1, oacc[nt][3] * il1);
    }
}

// ---------------------------------------------------------------------------
// Launch
// inputs: 0:q 1:k 2:v 3:mask 4:w_q 5:w_k 6:w_v 7:w_o ; out: [B,S,D] f32
// ---------------------------------------------------------------------------
extern "C" void kernel_launch(void* const* d_in, const int* in_sizes, int n_in,
                              void* d_out, int out_size)
{
    const float* q   = (const float*)d_in[0];
    const float* k   = (const float*)d_in[1];
    const float* v   = (const float*)d_in[2];
    // d_in[3] = mask (causal tril; handled analytically in-kernel)
    const float* w_q = (const float*)d_in[4];
    const float* w_k = (const float*)d_in[5];
    const float* w_v = (const float*)d_in[6];
    const float* w_o = (const float*)d_in[7];
    float* out = (float*)d_out;

    __half *q16, *k16, *v16, *w16, *qkv, *gX;
    cudaGetSymbolAddress((void**)&q16, g_q16);
    cudaGetSymbolAddress((void**)&k16, g_k16);
    cudaGetSymbolAddress((void**)&v16, g_v16);
    cudaGetSymbolAddress((void**)&w16, g_w16);
    cudaGetSymbolAddress((void**)&qkv, g_QKV);
    cudaGetSymbolAddress((void**)&gX, g_X);

    // fp32 -> fp16 conversions (2 fused launches, 4-way ILP; w_q pre-scaled)
    const int nx4 = QKV_ELEMS / 4;       // 2M float4 per q/k/v
    const int nw4 = DD * DD / 4;         // 256K float4 per weight
    cvt16_3<<<dim3(512, 1, 3), 256>>>((const float4*)q, (const float4*)k,
                                      (const float4*)v, (uint2*)q16,
                                      (uint2*)k16, (uint2*)v16, nx4);
    cvt16_4<<<dim3(256, 1, 4), 256>>>((const float4*)w_q, (const float4*)w_k,
                                      (const float4*)w_v, (const float4*)w_o,
                                      (uint2*)w16, nw4);

    const int gsmem = 3 * GEMM_BUF_BYTES;      // 98304 B
    cudaFuncSetAttribute(gemm_qkv, cudaFuncAttributeMaxDynamicSharedMemorySize, gsmem);
    cudaFuncSetAttribute(gemm_out, cudaFuncAttributeMaxDynamicSharedMemorySize, gsmem);
    cudaFuncSetAttribute(flash_h, cudaFuncAttributeMaxDynamicSharedMemorySize, FLASH_SMEM);

    // all three projections in ONE launch (single tail wave)
    gemm_qkv<<<dim3(DD / 128, MROWS / 128, 3), 256, gsmem>>>(q16, k16, v16, w16, qkv);

    flash_h<<<dim3(SS / 128, BB * HH), 256, FLASH_SMEM>>>(qkv, qkv + QKV_ELEMS,
                                                          qkv + 2 * QKV_ELEMS, gX);

    gemm_out<<<dim3(DD / 128, MROWS / 128), 256, gsmem>>>(gX, w16 + 3 * DD * DD, out);
}